// round 2
// baseline (speedup 1.0000x reference)
#include <cuda_runtime.h>
#include <math.h>

#define BSZ   4096
#define DIM   768
#define COMPS 16384
#define GRD   128      // SOM grid is 128 x 128
#define NT    128      // number of 128-wide comp tiles = COMPS/128

// ---------------- device scratch (no allocations allowed) ----------------
__device__ float g_T[COMPS * DIM];   // scatter buffer -> conv in-place -> V
__device__ float g_wn[COMPS];        // ||w_c||^2
__device__ float g_cnt[COMPS];       // BMU hit counts (float for conv)
__device__ float g_s1[COMPS];        // count conv intermediate
__device__ float g_s[COMPS];         // sum_b f(u_b, c) (no alpha)
__device__ float g_G[GRD * GRD];     // Gaussian matrix G[a*128+b] = exp(-(a-b)^2/sig^2)
__device__ float g_pmin[BSZ * NT];   // per (row, comp-tile) partial min
__device__ int   g_pidx[BSZ * NT];
__device__ int   g_bmu[BSZ];

// ---------------- zero scratch ----------------
__global__ void zero_kernel() {
    int i = blockIdx.x * blockDim.x + threadIdx.x;
    if (i < COMPS * DIM) g_T[i] = 0.f;
    if (i < COMPS) g_cnt[i] = 0.f;
}

// ---------------- ||w||^2 per codebook row (1 warp / row) ----------------
__global__ void wnorm_kernel(const float* __restrict__ W) {
    int row  = blockIdx.x * 8 + (threadIdx.x >> 5);
    int lane = threadIdx.x & 31;
    const float* wr = W + (size_t)row * DIM;
    float s = 0.f;
    for (int d = lane; d < DIM; d += 32) { float v = wr[d]; s = fmaf(v, v, s); }
    #pragma unroll
    for (int o = 16; o; o >>= 1) s += __shfl_xor_sync(0xffffffffu, s, o);
    if (lane == 0) g_wn[row] = s;
}

// ---------------- Gaussian matrix (depends on device-resident `it`) -------
__global__ void gmat_kernel(const int* __restrict__ itp) {
    float decay = 1.f - (float)(*itp) / 1000.f;
    float sig = 64.f * decay;                 // SIGMA = max(M,N)/2 = 64
    int a = blockIdx.x, b = threadIdx.x;
    float d = (float)(a - b);
    g_G[a * GRD + b] = expf(-(d * d) / (sig * sig));
}

// ---------------- BMU GEMM: 128x128x8 tiles, fused per-tile argmin --------
__global__ __launch_bounds__(256) void bmu_kernel(const float* __restrict__ X,
                                                  const float* __restrict__ W) {
    __shared__ float Xs[8][128];
    __shared__ float Ws[8][128];
    __shared__ float sv[128][16];
    __shared__ int   si[128][16];

    int t  = threadIdx.x;
    int tx = t & 15, ty = t >> 4;
    int bx = blockIdx.x, by = blockIdx.y;

    float acc[8][8];
    #pragma unroll
    for (int i = 0; i < 8; i++)
        #pragma unroll
        for (int j = 0; j < 8; j++) acc[i][j] = 0.f;

    int lrow = t >> 1;            // 0..127
    int lk4  = (t & 1) * 4;       // 0 or 4
    const float* Xp = X + (size_t)(by * 128 + lrow) * DIM + lk4;
    const float* Wp = W + (size_t)(bx * 128 + lrow) * DIM + lk4;

    for (int k0 = 0; k0 < DIM; k0 += 8) {
        float4 xv = *(const float4*)(Xp + k0);
        float4 wv = *(const float4*)(Wp + k0);
        if (k0) __syncthreads();
        Xs[lk4 + 0][lrow] = xv.x; Xs[lk4 + 1][lrow] = xv.y;
        Xs[lk4 + 2][lrow] = xv.z; Xs[lk4 + 3][lrow] = xv.w;
        Ws[lk4 + 0][lrow] = wv.x; Ws[lk4 + 1][lrow] = wv.y;
        Ws[lk4 + 2][lrow] = wv.z; Ws[lk4 + 3][lrow] = wv.w;
        __syncthreads();
        #pragma unroll
        for (int k = 0; k < 8; k++) {
            float4 a0 = *(const float4*)&Xs[k][ty * 4];
            float4 a1 = *(const float4*)&Xs[k][ty * 4 + 64];
            float4 b0 = *(const float4*)&Ws[k][tx * 4];
            float4 b1 = *(const float4*)&Ws[k][tx * 4 + 64];
            float a[8] = {a0.x, a0.y, a0.z, a0.w, a1.x, a1.y, a1.z, a1.w};
            float b[8] = {b0.x, b0.y, b0.z, b0.w, b1.x, b1.y, b1.z, b1.w};
            #pragma unroll
            for (int i = 0; i < 8; i++)
                #pragma unroll
                for (int j = 0; j < 8; j++)
                    acc[i][j] = fmaf(a[i], b[j], acc[i][j]);
        }
    }

    // d2 = ||w||^2 - 2 x.w  (||x||^2 constant per row, irrelevant for argmin)
    float rmin[8]; int ridx[8];
    #pragma unroll
    for (int i = 0; i < 8; i++) { rmin[i] = 3.4e38f; ridx[i] = 0x7fffffff; }
    #pragma unroll
    for (int j = 0; j < 8; j++) {
        int c  = (j < 4) ? (tx * 4 + j) : (64 + tx * 4 + (j - 4));
        int gc = bx * 128 + c;
        float wn = g_wn[gc];
        #pragma unroll
        for (int i = 0; i < 8; i++) {
            float d2 = wn - 2.f * acc[i][j];
            if (d2 < rmin[i] || (d2 == rmin[i] && gc < ridx[i])) {
                rmin[i] = d2; ridx[i] = gc;
            }
        }
    }
    __syncthreads();
    #pragma unroll
    for (int i = 0; i < 8; i++) {
        int r = (i < 4) ? (ty * 4 + i) : (64 + ty * 4 + (i - 4));
        sv[r][tx] = rmin[i]; si[r][tx] = ridx[i];
    }
    __syncthreads();
    if (t < 128) {
        float bv = sv[t][0]; int bi = si[t][0];
        #pragma unroll
        for (int j = 1; j < 16; j++) {
            float v = sv[t][j]; int ii = si[t][j];
            if (v < bv || (v == bv && ii < bi)) { bv = v; bi = ii; }
        }
        g_pmin[(size_t)(by * 128 + t) * NT + bx] = bv;
        g_pidx[(size_t)(by * 128 + t) * NT + bx] = bi;
    }
}

// ---------------- reduce 128 partials per batch row ----------------
__global__ void bmu_reduce_kernel() {
    __shared__ float sv[128];
    __shared__ int   si[128];
    int b = blockIdx.x, t = threadIdx.x;
    sv[t] = g_pmin[(size_t)b * NT + t];
    si[t] = g_pidx[(size_t)b * NT + t];
    __syncthreads();
    for (int s = 64; s; s >>= 1) {
        if (t < s) {
            float v = sv[t + s]; int ii = si[t + s];
            if (v < sv[t] || (v == sv[t] && ii < si[t])) { sv[t] = v; si[t] = ii; }
        }
        __syncthreads();
    }
    if (t == 0) g_bmu[b] = si[0];
}

// ---------------- scatter x_b into its BMU cell ----------------
__global__ void scatter_kernel(const float* __restrict__ X) {
    int b = blockIdx.x;
    int u = g_bmu[b];
    const float* xr = X + (size_t)b * DIM;
    float* tr = g_T + (size_t)u * DIM;
    for (int d = threadIdx.x; d < DIM; d += blockDim.x)
        atomicAdd(&tr[d], xr[d]);
    if (threadIdx.x == 0) atomicAdd(&g_cnt[u], 1.f);
}

// ---------------- separable Gaussian "conv" = 128x128 matmul, in place ----
// block handles ALL 128 output rows for a 64-column slice; reads complete
// before writes, and each (row-axis, col-slice) region is owned by 1 block.
__global__ __launch_bounds__(256) void conv_kernel(int rstride) {
    __shared__ float Ts[16][64];
    __shared__ float Gs[16][128];
    int t  = threadIdx.x;
    size_t base = (size_t)blockIdx.y * (GRD * DIM) + (size_t)blockIdx.x * 64;
    int cg = t & 15;        // cols cg*4 .. +3
    int rg = t >> 4;        // rows rg*8 .. +7
    int lk = t >> 4;        // loader k
    int lc = (t & 15) * 4;  // loader col
    int gi = (t & 15) * 8;  // loader G col

    float acc[8][4];
    #pragma unroll
    for (int r = 0; r < 8; r++)
        #pragma unroll
        for (int c = 0; c < 4; c++) acc[r][c] = 0.f;

    for (int k0 = 0; k0 < GRD; k0 += 16) {
        if (k0) __syncthreads();
        *(float4*)&Ts[lk][lc]     = *(const float4*)&g_T[base + (size_t)(k0 + lk) * rstride + lc];
        // G is symmetric: Gs[k][i'] = G[(k0+k)*128 + i'] (contiguous loads)
        *(float4*)&Gs[lk][gi]     = *(const float4*)&g_G[(k0 + lk) * GRD + gi];
        *(float4*)&Gs[lk][gi + 4] = *(const float4*)&g_G[(k0 + lk) * GRD + gi + 4];
        __syncthreads();
        #pragma unroll
        for (int k = 0; k < 16; k++) {
            float4 tv = *(const float4*)&Ts[k][cg * 4];
            float tc[4] = {tv.x, tv.y, tv.z, tv.w};
            #pragma unroll
            for (int r = 0; r < 8; r++) {
                float g = Gs[k][rg * 8 + r];
                #pragma unroll
                for (int c = 0; c < 4; c++)
                    acc[r][c] = fmaf(g, tc[c], acc[r][c]);
            }
        }
    }
    #pragma unroll
    for (int r = 0; r < 8; r++) {
        float4 o = make_float4(acc[r][0], acc[r][1], acc[r][2], acc[r][3]);
        *(float4*)&g_T[base + (size_t)(rg * 8 + r) * rstride + cg * 4] = o;
    }
}

// ---------------- tiny convs for counts -> s[c] ----------------
__global__ void convs1_kernel() {
    int ip = blockIdx.x, j = threadIdx.x;
    float s = 0.f;
    for (int i = 0; i < GRD; i++)
        s = fmaf(g_G[ip * GRD + i], g_cnt[i * GRD + j], s);
    g_s1[ip * GRD + j] = s;
}
__global__ void convs2_kernel() {
    int i = blockIdx.x, jp = threadIdx.x;
    float s = 0.f;
    for (int j = 0; j < GRD; j++)
        s = fmaf(g_G[j * GRD + jp], g_s1[i * GRD + j], s);   // G symmetric
    g_s[i * GRD + jp] = s;
}

// ---------------- final: out = w*(1 - alpha*s) + alpha*V ----------------
__global__ void final_kernel(const float* __restrict__ W, float* __restrict__ out,
                             const int* __restrict__ itp) {
    float decay = 1.f - (float)(*itp) / 1000.f;
    float alpha = 0.3f * decay;
    int idx = blockIdx.x * blockDim.x + threadIdx.x;
    int i4 = idx * 4;
    if (i4 >= COMPS * DIM) return;
    int c = i4 / DIM;                 // DIM % 4 == 0 -> all 4 lanes same c
    float m = 1.f - alpha * g_s[c];
    float4 w = *(const float4*)(W + i4);
    float4 v = *(const float4*)(g_T + i4);
    float4 o = make_float4(w.x * m + alpha * v.x,
                           w.y * m + alpha * v.y,
                           w.z * m + alpha * v.z,
                           w.w * m + alpha * v.w);
    *(float4*)(out + i4) = o;
}

// ---------------- launch ----------------
extern "C" void kernel_launch(void* const* d_in, const int* in_sizes, int n_in,
                              void* d_out, int out_size) {
    const float* X   = (const float*)d_in[0];   // embedded [4096, 768]
    const float* W   = (const float*)d_in[1];   // weights  [16384, 768]
    const int*   itp = (const int*)d_in[2];     // it (scalar, device)
    float* out = (float*)d_out;

    zero_kernel<<<(COMPS * DIM + 255) / 256, 256>>>();
    wnorm_kernel<<<COMPS / 8, 256>>>(W);
    gmat_kernel<<<GRD, GRD>>>(itp);

    dim3 gb(NT, BSZ / 128);
    bmu_kernel<<<gb, 256>>>(X, W);
    bmu_reduce_kernel<<<BSZ, 128>>>();
    scatter_kernel<<<BSZ, 256>>>(X);

    // conv along grid-i (row stride = 128*768), then grid-j (row stride = 768)
    conv_kernel<<<dim3(GRD * DIM / 64, 1), 256>>>(GRD * DIM);
    conv_kernel<<<dim3(DIM / 64, GRD), 256>>>(DIM);
    convs1_kernel<<<GRD, GRD>>>();
    convs2_kernel<<<GRD, GRD>>>();

    final_kernel<<<(COMPS * DIM / 4 + 255) / 256, 256>>>(W, out, itp);
}

// round 4
// speedup vs baseline: 2.0431x; 2.0431x over previous
#include <cuda_runtime.h>
#include <cuda_bf16.h>
#include <math.h>
#include <cstdint>

#define BSZ   4096
#define DIM   768
#define COMPS 16384
#define GRD   128
#define NTC   128       // comps tiles of 128

// ---------------- device scratch ----------------
__device__ float g_T[COMPS * DIM];
__device__ float g_wn[COMPS];
__device__ float g_cnt[COMPS];
__device__ float g_s1[COMPS];
__device__ float g_s[COMPS];
__device__ float g_G[GRD * GRD];
__device__ float g_pmin[BSZ * NTC];
__device__ int   g_pidx[BSZ * NTC];
__device__ int   g_bmu[BSZ];
__device__ __nv_bfloat16 g_Xh[BSZ * DIM];
__device__ __nv_bfloat16 g_Xl[BSZ * DIM];
__device__ __nv_bfloat16 g_Wh[COMPS * DIM];
__device__ __nv_bfloat16 g_Wl[COMPS * DIM];

// ---------------- helpers ----------------
__device__ __forceinline__ uint32_t smem_to_u32(const void* p) {
    uint32_t a;
    asm("{ .reg .u64 t; cvta.to.shared.u64 t, %1; cvt.u32.u64 %0, t; }" : "=r"(a) : "l"(p));
    return a;
}
__device__ __forceinline__ void cp_async16(uint32_t dst, const void* src) {
    asm volatile("cp.async.cg.shared.global [%0], [%1], 16;" :: "r"(dst), "l"(src));
}
__device__ __forceinline__ uint32_t lds32(uint32_t a) {
    uint32_t v;
    asm volatile("ld.shared.b32 %0, [%1];" : "=r"(v) : "r"(a));
    return v;
}
__device__ __forceinline__ void mma_bf16(float* d, const uint32_t* a, const uint32_t* b) {
    asm volatile(
        "mma.sync.aligned.m16n8k16.row.col.f32.bf16.bf16.f32 "
        "{%0,%1,%2,%3}, {%4,%5,%6,%7}, {%8,%9}, {%0,%1,%2,%3};"
        : "+f"(d[0]), "+f"(d[1]), "+f"(d[2]), "+f"(d[3])
        : "r"(a[0]), "r"(a[1]), "r"(a[2]), "r"(a[3]), "r"(b[0]), "r"(b[1]));
}

// ---------------- misc small kernels ----------------
__global__ void zero_kernel() {
    int i = blockIdx.x * blockDim.x + threadIdx.x;
    if (i < COMPS * DIM) g_T[i] = 0.f;
    if (i < COMPS) g_cnt[i] = 0.f;
}

__global__ void wnorm_kernel(const float* __restrict__ W) {
    int row = blockIdx.x * 8 + (threadIdx.x >> 5);
    int lane = threadIdx.x & 31;
    const float* wr = W + (size_t)row * DIM;
    float s = 0.f;
    for (int d = lane; d < DIM; d += 32) { float v = wr[d]; s = fmaf(v, v, s); }
    #pragma unroll
    for (int o = 16; o; o >>= 1) s += __shfl_xor_sync(0xffffffffu, s, o);
    if (lane == 0) g_wn[row] = s;
}

__global__ void gmat_kernel(const int* __restrict__ itp) {
    float decay = 1.f - (float)(*itp) / 1000.f;
    float sig = 64.f * decay;
    int a = blockIdx.x, b = threadIdx.x;
    float d = (float)(a - b);
    g_G[a * GRD + b] = expf(-(d * d) / (sig * sig));
}

// fp32 -> (bf16 hi, bf16 lo) split
__global__ void split_kernel(const float* __restrict__ src, __nv_bfloat16* __restrict__ dh,
                             __nv_bfloat16* __restrict__ dl, int n4) {
    int i = blockIdx.x * blockDim.x + threadIdx.x;
    if (i >= n4) return;
    float4 v = *(const float4*)(src + i * 4);
    float x[4] = {v.x, v.y, v.z, v.w};
    ushort4 hh, ll;
    unsigned short* hp = &hh.x; unsigned short* lp = &ll.x;
    #pragma unroll
    for (int k = 0; k < 4; k++) {
        __nv_bfloat16 h = __float2bfloat16(x[k]);
        __nv_bfloat16 l = __float2bfloat16(x[k] - __bfloat162float(h));
        hp[k] = __bfloat16_as_ushort(h);
        lp[k] = __bfloat16_as_ushort(l);
    }
    *(ushort4*)(dh + (size_t)i * 4) = hh;
    *(ushort4*)(dl + (size_t)i * 4) = ll;
}

// ---------------- BMU GEMM via mma.sync bf16 (3-GEMM hi/lo split) --------
// CTA tile: 128(X) x 128(W), K chunks of 32, double-buffered cp.async.
// smem: per stage 4 tiles [128 rows x 40 halfs] (Ah, Al, Bh, Bl) = 40960B;
// 2 stages = 81920; wns @81920 (512B); red_v @82432 (2048B); red_i @84480.
#define TILE_B   10240
#define STAGE_B  40960
#define BMU_SMEM 86528

__global__ __launch_bounds__(256, 2) void bmu_mma_kernel() {
    extern __shared__ char sm[];
    const uint32_t sb = smem_to_u32(sm);
    const int t = threadIdx.x, lane = t & 31, w = t >> 5;
    const int wm = w >> 2, wn_ = w & 3;
    const int bx = blockIdx.x, by = blockIdx.y;
    const int rowX = by * 128, rowW = bx * 128;

    float* wns   = (float*)(sm + 81920);
    float* red_v = (float*)(sm + 82432);
    int*   red_i = (int*)(sm + 84480);
    if (t < 128) wns[t] = g_wn[rowW + t];

    float acc[4][4][4];
    #pragma unroll
    for (int mi = 0; mi < 4; mi++)
        #pragma unroll
        for (int ni = 0; ni < 4; ni++)
            #pragma unroll
            for (int k = 0; k < 4; k++) acc[mi][ni][k] = 0.f;

    // loader: 512 uint4 per tile, 2 per thread per tile
    const int lr0 = t >> 2, lg = t & 3;   // thread covers rows lr0, lr0+64
    auto load_stage = [&](int s, int c) {
        uint32_t base = sb + s * STAGE_B;
        #pragma unroll
        for (int i = 0; i < 2; i++) {
            int r = lr0 + i * 64;
            uint32_t so = (uint32_t)(r * 80 + lg * 16);
            size_t goA = (size_t)(rowX + r) * DIM + c * 32 + lg * 8;
            size_t goB = (size_t)(rowW + r) * DIM + c * 32 + lg * 8;
            cp_async16(base + so,              g_Xh + goA);
            cp_async16(base + TILE_B + so,     g_Xl + goA);
            cp_async16(base + 2 * TILE_B + so, g_Wh + goB);
            cp_async16(base + 3 * TILE_B + so, g_Wl + goB);
        }
    };

    const int arow = lane >> 2, acol = (lane & 3) * 2;

    auto compute = [&](int s, int kk) {
        uint32_t Ah = sb + s * STAGE_B;
        uint32_t Al = Ah + TILE_B;
        uint32_t Bh = Ah + 2 * TILE_B;
        uint32_t Bl = Ah + 3 * TILE_B;

        uint32_t bh[4][2], bl[4][2];
        #pragma unroll
        for (int ni = 0; ni < 4; ni++) {
            uint32_t off = (uint32_t)(((wn_ * 32 + ni * 8 + arow) * 40 + kk + acol) * 2);
            bh[ni][0] = lds32(Bh + off); bh[ni][1] = lds32(Bh + off + 16);
            bl[ni][0] = lds32(Bl + off); bl[ni][1] = lds32(Bl + off + 16);
        }
        uint32_t a[4][4];
        #pragma unroll
        for (int mi = 0; mi < 4; mi++) {
            uint32_t off = (uint32_t)(((wm * 64 + mi * 16 + arow) * 40 + kk + acol) * 2);
            a[mi][0] = lds32(Ah + off);        a[mi][1] = lds32(Ah + off + 640);
            a[mi][2] = lds32(Ah + off + 16);   a[mi][3] = lds32(Ah + off + 656);
        }
        #pragma unroll
        for (int mi = 0; mi < 4; mi++)
            #pragma unroll
            for (int ni = 0; ni < 4; ni++) mma_bf16(acc[mi][ni], a[mi], bh[ni]);
        #pragma unroll
        for (int mi = 0; mi < 4; mi++)
            #pragma unroll
            for (int ni = 0; ni < 4; ni++) mma_bf16(acc[mi][ni], a[mi], bl[ni]);
        #pragma unroll
        for (int mi = 0; mi < 4; mi++) {
            uint32_t off = (uint32_t)(((wm * 64 + mi * 16 + arow) * 40 + kk + acol) * 2);
            a[mi][0] = lds32(Al + off);        a[mi][1] = lds32(Al + off + 640);
            a[mi][2] = lds32(Al + off + 16);   a[mi][3] = lds32(Al + off + 656);
        }
        #pragma unroll
        for (int mi = 0; mi < 4; mi++)
            #pragma unroll
            for (int ni = 0; ni < 4; ni++) mma_bf16(acc[mi][ni], a[mi], bh[ni]);
    };

    load_stage(0, 0);
    asm volatile("cp.async.commit_group;");
    for (int c = 0; c < 24; c++) {
        if (c < 23) {
            load_stage((c + 1) & 1, c + 1);
            asm volatile("cp.async.commit_group;");
            asm volatile("cp.async.wait_group 1;");
        } else {
            asm volatile("cp.async.wait_group 0;");
        }
        __syncthreads();
        compute(c & 1, 0);
        compute(c & 1, 16);
        __syncthreads();
    }

    // epilogue: d2 = wn - 2*dot, per-row argmin
    #pragma unroll
    for (int mi = 0; mi < 4; mi++) {
        #pragma unroll
        for (int h = 0; h < 2; h++) {
            float bv = 3.4e38f; int bi = 0x7fffffff;
            #pragma unroll
            for (int ni = 0; ni < 4; ni++) {
                #pragma unroll
                for (int cc = 0; cc < 2; cc++) {
                    int nl = wn_ * 32 + ni * 8 + (lane & 3) * 2 + cc;
                    float d2 = wns[nl] - 2.f * acc[mi][ni][h * 2 + cc];
                    if (d2 < bv) { bv = d2; bi = rowW + nl; }
                }
            }
            // reduce over the 4 lanes sharing this row (lane&3)
            #pragma unroll
            for (int o = 1; o < 4; o <<= 1) {
                float ov = __shfl_xor_sync(0xffffffffu, bv, o);
                int   oi = __shfl_xor_sync(0xffffffffu, bi, o);
                if (ov < bv || (ov == bv && oi < bi)) { bv = ov; bi = oi; }
            }
            if ((lane & 3) == 0) {
                int rl = wm * 64 + mi * 16 + arow + h * 8;
                red_v[rl * 4 + wn_] = bv;
                red_i[rl * 4 + wn_] = bi;
            }
        }
    }
    __syncthreads();
    if (t < 128) {
        float bv = red_v[t * 4]; int bi = red_i[t * 4];
        #pragma unroll
        for (int j = 1; j < 4; j++) {
            float v = red_v[t * 4 + j]; int ii = red_i[t * 4 + j];
            if (v < bv || (v == bv && ii < bi)) { bv = v; bi = ii; }
        }
        g_pmin[(size_t)(rowX + t) * NTC + bx] = bv;
        g_pidx[(size_t)(rowX + t) * NTC + bx] = bi;
    }
}

// ---------------- reduce 128 partials per batch row ----------------
__global__ void bmu_reduce_kernel() {
    __shared__ float sv[128];
    __shared__ int   si[128];
    int b = blockIdx.x, t = threadIdx.x;
    sv[t] = g_pmin[(size_t)b * NTC + t];
    si[t] = g_pidx[(size_t)b * NTC + t];
    __syncthreads();
    for (int s = 64; s; s >>= 1) {
        if (t < s) {
            float v = sv[t + s]; int ii = si[t + s];
            if (v < sv[t] || (v == sv[t] && ii < si[t])) { sv[t] = v; si[t] = ii; }
        }
        __syncthreads();
    }
    if (t == 0) g_bmu[b] = si[0];
}

__global__ void scatter_kernel(const float* __restrict__ X) {
    int b = blockIdx.x;
    int u = g_bmu[b];
    const float* xr = X + (size_t)b * DIM;
    float* tr = g_T + (size_t)u * DIM;
    for (int d = threadIdx.x; d < DIM; d += blockDim.x)
        atomicAdd(&tr[d], xr[d]);
    if (threadIdx.x == 0) atomicAdd(&g_cnt[u], 1.f);
}

// ---------------- separable Gaussian conv (128-matmul), in place ----------
__global__ __launch_bounds__(256) void conv_kernel(int rstride) {
    __shared__ float Ts[16][64];
    __shared__ float Gs[16][128];
    int t = threadIdx.x;
    size_t base = (size_t)blockIdx.y * (GRD * DIM) + (size_t)blockIdx.x * 64;
    int cg = t & 15, rg = t >> 4;
    int lk = t >> 4, lc = (t & 15) * 4, gi = (t & 15) * 8;

    float acc[8][4];
    #pragma unroll
    for (int r = 0; r < 8; r++)
        #pragma unroll
        for (int c = 0; c < 4; c++) acc[r][c] = 0.f;

    for (int k0 = 0; k0 < GRD; k0 += 16) {
        if (k0) __syncthreads();
        *(float4*)&Ts[lk][lc]     = *(const float4*)&g_T[base + (size_t)(k0 + lk) * rstride + lc];
        *(float4*)&Gs[lk][gi]     = *(const float4*)&g_G[(k0 + lk) * GRD + gi];
        *(float4*)&Gs[lk][gi + 4] = *(const float4*)&g_G[(k0 + lk) * GRD + gi + 4];
        __syncthreads();
        #pragma unroll
        for (int k = 0; k < 16; k++) {
            float4 tv = *(const float4*)&Ts[k][cg * 4];
            float tc[4] = {tv.x, tv.y, tv.z, tv.w};
            #pragma unroll
            for (int r = 0; r < 8; r++) {
                float g = Gs[k][rg * 8 + r];
                #pragma unroll
                for (int c = 0; c < 4; c++)
                    acc[r][c] = fmaf(g, tc[c], acc[r][c]);
            }
        }
    }
    #pragma unroll
    for (int r = 0; r < 8; r++) {
        float4 o = make_float4(acc[r][0], acc[r][1], acc[r][2], acc[r][3]);
        *(float4*)&g_T[base + (size_t)(rg * 8 + r) * rstride + cg * 4] = o;
    }
}

__global__ void convs1_kernel() {
    int ip = blockIdx.x, j = threadIdx.x;
    float s = 0.f;
    for (int i = 0; i < GRD; i++)
        s = fmaf(g_G[ip * GRD + i], g_cnt[i * GRD + j], s);
    g_s1[ip * GRD + j] = s;
}
__global__ void convs2_kernel() {
    int i = blockIdx.x, jp = threadIdx.x;
    float s = 0.f;
    for (int j = 0; j < GRD; j++)
        s = fmaf(g_G[j * GRD + jp], g_s1[i * GRD + j], s);
    g_s[i * GRD + jp] = s;
}

__global__ void final_kernel(const float* __restrict__ W, float* __restrict__ out,
                             const int* __restrict__ itp) {
    float decay = 1.f - (float)(*itp) / 1000.f;
    float alpha = 0.3f * decay;
    int idx = blockIdx.x * blockDim.x + threadIdx.x;
    int i4 = idx * 4;
    if (i4 >= COMPS * DIM) return;
    int c = i4 / DIM;
    float m = 1.f - alpha * g_s[c];
    float4 w = *(const float4*)(W + i4);
    float4 v = *(const float4*)(g_T + i4);
    float4 o = make_float4(w.x * m + alpha * v.x, w.y * m + alpha * v.y,
                           w.z * m + alpha * v.z, w.w * m + alpha * v.w);
    *(float4*)(out + i4) = o;
}

// ---------------- launch ----------------
extern "C" void kernel_launch(void* const* d_in, const int* in_sizes, int n_in,
                              void* d_out, int out_size) {
    const float* X   = (const float*)d_in[0];
    const float* W   = (const float*)d_in[1];
    const int*   itp = (const int*)d_in[2];
    float* out = (float*)d_out;

    cudaFuncSetAttribute(bmu_mma_kernel, cudaFuncAttributeMaxDynamicSharedMemorySize, BMU_SMEM);

    __nv_bfloat16 *xh, *xl, *wh, *wl;
    cudaGetSymbolAddress((void**)&xh, g_Xh);
    cudaGetSymbolAddress((void**)&xl, g_Xl);
    cudaGetSymbolAddress((void**)&wh, g_Wh);
    cudaGetSymbolAddress((void**)&wl, g_Wl);

    zero_kernel<<<(COMPS * DIM + 255) / 256, 256>>>();
    wnorm_kernel<<<COMPS / 8, 256>>>(W);
    gmat_kernel<<<GRD, GRD>>>(itp);
    split_kernel<<<(BSZ * DIM / 4 + 255) / 256, 256>>>(X, xh, xl, BSZ * DIM / 4);
    split_kernel<<<(COMPS * DIM / 4 + 255) / 256, 256>>>(W, wh, wl, COMPS * DIM / 4);

    bmu_mma_kernel<<<dim3(NTC, BSZ / 128), 256, BMU_SMEM>>>();
    bmu_reduce_kernel<<<BSZ, 128>>>();
    scatter_kernel<<<BSZ, 256>>>(X);

    conv_kernel<<<dim3(GRD * DIM / 64, 1), 256>>>(GRD * DIM);
    conv_kernel<<<dim3(DIM / 64, GRD), 256>>>(DIM);
    convs1_kernel<<<GRD, GRD>>>();
    convs2_kernel<<<GRD, GRD>>>();

    final_kernel<<<(COMPS * DIM / 4 + 255) / 256, 256>>>(W, out, itp);
}